// round 17
// baseline (speedup 1.0000x reference)
#include <cuda_runtime.h>
#include <cstddef>
#include <cstdint>

#define NP 4
#define NS 4
#define NC 64
#define NF 64
#define NB 64
// PS = 16, PSC = 1024, per-psc KQ block = F*C*F = 262144 floats

__device__ float g_weights[NP * NS * NC * NC];   // softmax(scores), 256 KB
__device__ float g_V[NB * NP * NS * NC * NF];    // V spill for unfused blocks
__device__ int   g_wcount[NP * NS];              // per-ps completion counters
__device__ int   g_done[NB * NP * NS];           // per-bp fused flag

// packed fp32x2 FMA: {d.lo,d.hi} += {a.lo*b.lo, a.hi*b.hi} — exact fp32, 2x rate
__device__ __forceinline__ void ffma2(unsigned long long& acc,
                                      unsigned long long a,
                                      unsigned long long b) {
    asm("fma.rn.f32x2 %0, %1, %2, %0;" : "+l"(acc) : "l"(a), "l"(b));
}
// pack one fp32 into both lanes of a 64-bit pair (ALU pipe, 1 instr)
__device__ __forceinline__ unsigned long long dup2(float w) {
    unsigned long long r;
    asm("mov.b64 %0, {%1, %1};" : "=l"(r) : "f"(w));
    return r;
}

#define R_STRIDE 68   // row stride (floats) for both smem regions; 16B-aligned

// ---------------------------------------------------------------------------
__global__ void reset_kernel() {
    const int t = threadIdx.x;
    if (t < NP * NS) g_wcount[t] = 0;
    g_done[t] = 0;   // blockDim = 1024 = NB*NP*NS
}

// ---------------------------------------------------------------------------
// Kernel 1: 2048 blocks x 1024 threads, roles interleaved by bid&1.
// EVEN blocks: KQ reduction (DRAM roofline) + fused softmax; publishes
//   weights then fence + atomicAdd on g_wcount[ps].
// ODD  blocks: GEMM1 (V = X@Wv^T). Then ONE non-blocking check of
//   g_wcount[ps]: if that ps's weights are already published, do GEMM2 here
//   (w via __ldcg), write out, mark done[bp]. Else spill V to g_V.
//   No spinning — worst case identical to the R9 structure.
// ---------------------------------------------------------------------------
__global__ void __launch_bounds__(1024, 2)
reduce_softmax_v_kernel(const float* __restrict__ kq,
                        const float* __restrict__ x,
                        const float* __restrict__ wv,
                        float* __restrict__ out) {
    __shared__ float sh[2 * NC * R_STRIDE];   // 34.8 KB, two [64][68] regions
    __shared__ int   sh_ready;

    const int bid = blockIdx.x;
    const int t   = threadIdx.x;

    if ((bid & 1) == 0) {
        // ---- role A: KQ reduction + softmax ----
        const int psc = bid >> 1;
        const int ps  = psc >> 6;
        const int d   = t >> 4;
        const int j   = t & 15;

        const float4* base =
            reinterpret_cast<const float4*>(kq + (size_t)psc * (NF * NC * NF))
            + (d * (NF / 4) + j);

        float4 acc = make_float4(0.f, 0.f, 0.f, 0.f);
#pragma unroll 4
        for (int f = 0; f < NF; ++f) {
            float4 v = __ldcs(base + f * (NC * NF / 4));
            acc.x += v.x; acc.y += v.y; acc.z += v.z; acc.w += v.w;
        }
        float s = (acc.x + acc.y) + (acc.z + acc.w);

        s += __shfl_xor_sync(0xffffffffu, s, 8);
        s += __shfl_xor_sync(0xffffffffu, s, 4);
        s += __shfl_xor_sync(0xffffffffu, s, 2);
        s += __shfl_xor_sync(0xffffffffu, s, 1);

        if (j == 0) sh[d] = s;
        __syncthreads();

        if (t < 32) {
            const float a = sh[t];
            const float b = sh[t + 32];
            float m = fmaxf(a, b);
#pragma unroll
            for (int off = 16; off > 0; off >>= 1)
                m = fmaxf(m, __shfl_xor_sync(0xffffffffu, m, off));
            const float ea = __expf(a - m);
            const float eb = __expf(b - m);
            float ssum = ea + eb;
#pragma unroll
            for (int off = 16; off > 0; off >>= 1)
                ssum += __shfl_xor_sync(0xffffffffu, ssum, off);
            const float inv = 1.0f / ssum;
            g_weights[psc * NC + t]      = ea * inv;
            g_weights[psc * NC + t + 32] = eb * inv;
            __threadfence();               // publish weights before counting
            __syncwarp();
            if (t == 0) atomicAdd(&g_wcount[ps], 1);
        }
    } else {
        // ---- role B: GEMM1 + opportunistic GEMM2 ----
        const int bp = bid >> 1;                    // = b*16 + ps
        const int b  = bp >> 4;
        const int ps = bp & 15;
        float* R1 = sh;                             // X[c][k] -> later w flat
        float* R2 = sh + NC * R_STRIDE;             // Wv^T[k][f] -> later V flat

        const float* xsrc = x + (size_t)bp * (NC * NF);
#pragma unroll
        for (int r = 0; r < 4; ++r) {
            const int idx = t + r * 1024;
            const int hi  = idx >> 6, lo = idx & 63;
            R1[hi * R_STRIDE + lo] = xsrc[idx];
            R2[lo * R_STRIDE + hi] = wv[idx];       // wv[f][k] -> WT[k][f]
        }
        __syncthreads();

        // GEMM1: V[c][4fq..] = sum_k X[c][k] * WvT[k][4fq..]
        const int c  = t >> 4;
        const int fq = t & 15;
        float4 vacc = make_float4(0.f, 0.f, 0.f, 0.f);
#pragma unroll 8
        for (int k = 0; k < NF; ++k) {
            const float  xk = R1[c * R_STRIDE + k];
            const float4 w4 = *reinterpret_cast<const float4*>(
                                  &R2[k * R_STRIDE + 4 * fq]);
            vacc.x += xk * w4.x; vacc.y += xk * w4.y;
            vacc.z += xk * w4.z; vacc.w += xk * w4.w;
        }

        // single non-blocking readiness check
        if (t == 0) sh_ready = atomicAdd(&g_wcount[ps], 0);
        __syncthreads();   // GEMM1 reads done + sh_ready visible

        if (sh_ready == NC) {
            // ---- fused GEMM2 ----
            __threadfence();
            // V flat into R2, w flat into R1 (both 16B-aligned, 64x64)
            *reinterpret_cast<float4*>(&R2[c * NF + 4 * fq]) = vacc;
            const float4* wsrc = reinterpret_cast<const float4*>(
                                     g_weights + (size_t)ps * (NC * NC));
            reinterpret_cast<float4*>(R1)[t] = __ldcg(wsrc + t);  // 1024 float4
            __syncthreads();

            unsigned long long o01 = 0ull, o23 = 0ull;
            const int frow = 4 * fq;
#pragma unroll 4
            for (int d4 = 0; d4 < NC / 4; ++d4) {
                const ulonglong2 v0 = *reinterpret_cast<const ulonglong2*>(&R2[(4 * d4 + 0) * NF + frow]);
                const ulonglong2 v1 = *reinterpret_cast<const ulonglong2*>(&R2[(4 * d4 + 1) * NF + frow]);
                const ulonglong2 v2 = *reinterpret_cast<const ulonglong2*>(&R2[(4 * d4 + 2) * NF + frow]);
                const ulonglong2 v3 = *reinterpret_cast<const ulonglong2*>(&R2[(4 * d4 + 3) * NF + frow]);
                const float4 w4 = *reinterpret_cast<const float4*>(
                                      &R1[c * NF + 4 * d4]);       // broadcast
                const unsigned long long wx = dup2(w4.x);
                const unsigned long long wy = dup2(w4.y);
                const unsigned long long wz = dup2(w4.z);
                const unsigned long long ww = dup2(w4.w);
                ffma2(o01, wx, v0.x);  ffma2(o23, wx, v0.y);
                ffma2(o01, wy, v1.x);  ffma2(o23, wy, v1.y);
                ffma2(o01, wz, v2.x);  ffma2(o23, wz, v2.y);
                ffma2(o01, ww, v3.x);  ffma2(o23, ww, v3.y);
            }

            float* orow = out + ((size_t)c * NB + b) * (NP * NS * NF)
                              + (size_t)ps * NF;
            float4 o;
            o.x = __uint_as_float((unsigned)(o01 & 0xffffffffull));
            o.y = __uint_as_float((unsigned)(o01 >> 32));
            o.z = __uint_as_float((unsigned)(o23 & 0xffffffffull));
            o.w = __uint_as_float((unsigned)(o23 >> 32));
            *reinterpret_cast<float4*>(&orow[frow]) = o;

            if (t == 0) g_done[bp] = 1;   // kernel boundary orders this
        } else {
            // ---- spill V for kernel 2 ----
            float4* vdst = reinterpret_cast<float4*>(g_V + (size_t)bp * (NC * NF));
            vdst[c * (NF / 4) + fq] = vacc;
        }
    }
}

// ---------------------------------------------------------------------------
// Kernel 2: R9 config (proven 17.4 us full-load): 1024 blocks x 128 thr,
// 8c x 4f tile, broadcast w LDS.128, conflict-free V LDS.128, dup2+FFMA2,
// natural regs. Early-exits on blocks already fused by kernel 1.
// ---------------------------------------------------------------------------
__global__ void __launch_bounds__(128)
attn_out_kernel(float* __restrict__ out) {
    const int blk = blockIdx.x;
    if (g_done[blk]) return;

    __shared__ float bufV[NC * NF];         // V[d][f], flat
    __shared__ float bufW[NC * (NF + 4)];   // w[c][d], stride 68

    const int b   = blk >> 4;
    const int ps  = blk & 15;
    const int t   = threadIdx.x;
    const int tcg = t >> 4;                 // 0..7
    const int tf  = t & 15;                 // 0..15

    const float4* vsrc = reinterpret_cast<const float4*>(g_V + (size_t)blk * (NC * NF));
    const float4* wsrc = reinterpret_cast<const float4*>(g_weights + (size_t)ps * (NC * NC));
    float4* bv4 = reinterpret_cast<float4*>(bufV);
#pragma unroll
    for (int r = 0; r < 8; ++r) {
        const int i4 = t + r * 128;                  // 0..1023 float4s
        bv4[i4] = vsrc[i4];
        reinterpret_cast<float4*>(&bufW[(i4 >> 4) * (NF + 4)])[i4 & 15] = wsrc[i4];
    }
    __syncthreads();

    unsigned long long o01[8], o23[8];
#pragma unroll
    for (int i = 0; i < 8; ++i) { o01[i] = 0ull; o23[i] = 0ull; }

    const int frow = 4 * tf;

#pragma unroll 4
    for (int d4 = 0; d4 < NC / 4; ++d4) {
        const ulonglong2 v0 = *reinterpret_cast<const ulonglong2*>(&bufV[(4 * d4 + 0) * NF + frow]);
        const ulonglong2 v1 = *reinterpret_cast<const ulonglong2*>(&bufV[(4 * d4 + 1) * NF + frow]);
        const ulonglong2 v2 = *reinterpret_cast<const ulonglong2*>(&bufV[(4 * d4 + 2) * NF + frow]);
        const ulonglong2 v3 = *reinterpret_cast<const ulonglong2*>(&bufV[(4 * d4 + 3) * NF + frow]);

#pragma unroll
        for (int i = 0; i < 8; ++i) {
            const float4 w4 = *reinterpret_cast<const float4*>(
                                  &bufW[(tcg + 8 * i) * (NF + 4) + 4 * d4]);
            const unsigned long long wx = dup2(w4.x);
            const unsigned long long wy = dup2(w4.y);
            const unsigned long long wz = dup2(w4.z);
            const unsigned long long ww = dup2(w4.w);
            ffma2(o01[i], wx, v0.x);  ffma2(o23[i], wx, v0.y);
            ffma2(o01[i], wy, v1.x);  ffma2(o23[i], wy, v1.y);
            ffma2(o01[i], wz, v2.x);  ffma2(o23[i], wz, v2.y);
            ffma2(o01[i], ww, v3.x);  ffma2(o23[i], ww, v3.y);
        }
    }

#pragma unroll
    for (int i = 0; i < 8; ++i) {
        const int c = tcg + 8 * i;
        float* orow = out + ((size_t)c * NB + b) * (NP * NS * NF) + (size_t)ps * NF;
        float4 o;
        o.x = __uint_as_float((unsigned)(o01[i] & 0xffffffffull));
        o.y = __uint_as_float((unsigned)(o01[i] >> 32));
        o.z = __uint_as_float((unsigned)(o23[i] & 0xffffffffull));
        o.w = __uint_as_float((unsigned)(o23[i] >> 32));
        *reinterpret_cast<float4*>(&orow[frow]) = o;
    }
}

// ---------------------------------------------------------------------------
extern "C" void kernel_launch(void* const* d_in, const int* in_sizes, int n_in,
                              void* d_out, int out_size) {
    const float* X  = (const float*)d_in[0];  // (B, P*S*C*F)
    const float* KQ = (const float*)d_in[1];  // (P,S,C,F,C,F) — 1 GB
    const float* Wv = (const float*)d_in[2];  // (F, F)
    float* out = (float*)d_out;               // (C, B, P*S*F)

    reset_kernel<<<1, 1024>>>();
    reduce_softmax_v_kernel<<<2048, 1024>>>(KQ, X, Wv, out);
    attn_out_kernel<<<NB * NP * NS, 128>>>(out);
}